// round 13
// baseline (speedup 1.0000x reference)
#include <cuda_runtime.h>
#include <cuda_bf16.h>
#include <cstdint>

// ---------------- problem constants ----------------
#define BATCH 8
#define CH    256
#define HH    96
#define WW    96
#define HWSZ  (HH*WW)        // 9216
#define NWD   12
#define LWIN  144
#define NWIN  1152
#define QW    64
#define NHEAD 8
#define HD    32
#define SCALE 0.1767766952966369f

// ---------------- device scratch ----------------
__device__ float g_xw[NWIN*QW*CH];         // [n][s][c]
__device__ float g_q [NWIN*QW*CH];         // Q projection
__device__ float g_z [NWIN*QW*CH];         // attn out + rpe (BCHW-flat)
__device__ float g_pool[NWIN*CH];          // pooled tokens
__device__ float g_poolpart[32*NWIN*CH];   // split-K partials (32 slices)
__device__ float g_kv[NWIN*2*CH];          // [bl][t*256 + head*32 + d]
__device__ float g_poolwT[CH*QW*CH];       // pool_w -> [o][s*256+c]

// ---------------- helpers ----------------
__device__ __forceinline__ uint32_t smem_u32(const void* p) {
    uint32_t a;
    asm("{ .reg .u64 t; cvta.to.shared.u64 t, %1; cvt.u32.u64 %0, t; }" : "=r"(a) : "l"(p));
    return a;
}
__device__ __forceinline__ void ldsm4(uint32_t* r, uint32_t addr) {
    asm volatile("ldmatrix.sync.aligned.m8n8.x4.shared.b16 {%0,%1,%2,%3}, [%4];"
        : "=r"(r[0]), "=r"(r[1]), "=r"(r[2]), "=r"(r[3]) : "r"(addr));
}
__device__ __forceinline__ void mma16816(float* c, const uint32_t* a, const uint32_t* b) {
    asm volatile("mma.sync.aligned.m16n8k16.row.col.f32.bf16.bf16.f32 "
        "{%0,%1,%2,%3}, {%4,%5,%6,%7}, {%8,%9}, {%0,%1,%2,%3};"
        : "+f"(c[0]), "+f"(c[1]), "+f"(c[2]), "+f"(c[3])
        : "r"(a[0]), "r"(a[1]), "r"(a[2]), "r"(a[3]), "r"(b[0]), "r"(b[1]));
}
__device__ __forceinline__ void cvt_hl(float4 v, uint2& h, uint2& l) {
    __nv_bfloat16 h0 = __float2bfloat16(v.x), h1 = __float2bfloat16(v.y);
    __nv_bfloat16 h2 = __float2bfloat16(v.z), h3 = __float2bfloat16(v.w);
    __nv_bfloat16 l0 = __float2bfloat16(v.x - __bfloat162float(h0));
    __nv_bfloat16 l1 = __float2bfloat16(v.y - __bfloat162float(h1));
    __nv_bfloat16 l2 = __float2bfloat16(v.z - __bfloat162float(h2));
    __nv_bfloat16 l3 = __float2bfloat16(v.w - __bfloat162float(h3));
    h.x = ((uint32_t)__bfloat16_as_ushort(h1) << 16) | __bfloat16_as_ushort(h0);
    h.y = ((uint32_t)__bfloat16_as_ushort(h3) << 16) | __bfloat16_as_ushort(h2);
    l.x = ((uint32_t)__bfloat16_as_ushort(l1) << 16) | __bfloat16_as_ushort(l0);
    l.y = ((uint32_t)__bfloat16_as_ushort(l3) << 16) | __bfloat16_as_ushort(l2);
}

// =============== HMMA NT GEMM (3-pass bf16 hi/lo, fp32-class accuracy) ===============
// C[m,n] = sum_k A[m*K+k] * B[n*K+k].  Block tile 128x128, BK=32, 8 warps (2x4),
// warp tile 64x32 via m16n8k16. grid = (N/128, M/128, splitK).
__global__ __launch_bounds__(256) void k_gemm_mma(
    const float* __restrict__ A, const float* __restrict__ B,
    float* __restrict__ C, const float* __restrict__ bias,
    int M, int K, int ldc, int kcount)
{
    __shared__ __align__(16) __nv_bfloat16 AsH[128][40];
    __shared__ __align__(16) __nv_bfloat16 AsL[128][40];
    __shared__ __align__(16) __nv_bfloat16 BsH[128][40];
    __shared__ __align__(16) __nv_bfloat16 BsL[128][40];

    const int t    = threadIdx.x;
    const int lane = t & 31;
    const int wid  = t >> 5;
    const int n0 = blockIdx.x * 128;
    const int m0 = blockIdx.y * 128;
    const int k0 = blockIdx.z * kcount;
    A += (size_t)m0 * K + k0;
    B += (size_t)n0 * K + k0;
    C += (size_t)blockIdx.z * M * ldc + (size_t)m0 * ldc + n0;
    const float* bp = bias ? bias + n0 : nullptr;

    const int wm = (wid >> 2) * 64;   // warp row offset: 0 / 64
    const int wn = (wid & 3) * 32;    // warp col offset: 0/32/64/96

    const uint32_t aH_base = smem_u32(AsH), aL_base = smem_u32(AsL);
    const uint32_t bH_base = smem_u32(BsH), bL_base = smem_u32(BsL);

    float acc[4][4][4] = {};

    const int rb = t >> 3;        // 0..31 row base
    const int jb = t & 7;         // float4 column group

    const int nChunks = kcount >> 5;
    for (int c = 0; c < nChunks; c++) {
        const float* Ag = A + c * 32;
        const float* Bg = B + c * 32;
        // ---- global -> smem with fp32 -> (hi, lo) bf16 split ----
        #pragma unroll
        for (int it = 0; it < 4; it++) {
            int r = it * 32 + rb;
            float4 va = *(const float4*)(Ag + (size_t)r * K + jb * 4);
            float4 vb = *(const float4*)(Bg + (size_t)r * K + jb * 4);
            uint2 h, l;
            cvt_hl(va, h, l);
            *(uint2*)((char*)AsH + r * 80 + jb * 8) = h;
            *(uint2*)((char*)AsL + r * 80 + jb * 8) = l;
            cvt_hl(vb, h, l);
            *(uint2*)((char*)BsH + r * 80 + jb * 8) = h;
            *(uint2*)((char*)BsL + r * 80 + jb * 8) = l;
        }
        __syncthreads();

        #pragma unroll
        for (int kk = 0; kk < 32; kk += 16) {
            uint32_t aH[4][4], aL[4][4], bH[2][4], bL[2][4];
            // A fragments: 4 m-tiles (16 rows each)
            #pragma unroll
            for (int mi = 0; mi < 4; mi++) {
                uint32_t off = (uint32_t)((wm + mi * 16 + (lane & 15)) * 80
                                          + (kk + ((lane >> 4) << 3)) * 2);
                ldsm4(aH[mi], aH_base + off);
                ldsm4(aL[mi], aL_base + off);
            }
            // B fragments: 2 ldsm.x4 cover 4 n8-tiles (32 cols)
            #pragma unroll
            for (int nj = 0; nj < 2; nj++) {
                uint32_t off = (uint32_t)((wn + nj * 16 + ((lane >> 4) << 3) + (lane & 7)) * 80
                                          + (kk + (((lane >> 3) & 1) << 3)) * 2);
                ldsm4(bH[nj], bH_base + off);
                ldsm4(bL[nj], bL_base + off);
            }
            #pragma unroll
            for (int mi = 0; mi < 4; mi++)
                #pragma unroll
                for (int ni = 0; ni < 4; ni++) {
                    const uint32_t* bh = &bH[ni >> 1][(ni & 1) * 2];
                    const uint32_t* bl = &bL[ni >> 1][(ni & 1) * 2];
                    mma16816(acc[mi][ni], aH[mi], bh);
                    mma16816(acc[mi][ni], aH[mi], bl);
                    mma16816(acc[mi][ni], aL[mi], bh);
                }
        }
        __syncthreads();
    }

    // ---- epilogue ----
    #pragma unroll
    for (int mi = 0; mi < 4; mi++)
        #pragma unroll
        for (int ni = 0; ni < 4; ni++) {
            int r0 = wm + mi * 16 + (lane >> 2);
            int cc = wn + ni * 8 + (lane & 3) * 2;
            float b0 = 0.f, b1 = 0.f;
            if (bp) { b0 = bp[cc]; b1 = bp[cc + 1]; }
            float2 v0 = make_float2(acc[mi][ni][0] + b0, acc[mi][ni][1] + b1);
            float2 v1 = make_float2(acc[mi][ni][2] + b0, acc[mi][ni][3] + b1);
            *(float2*)(C + (size_t)r0 * ldc + cc) = v0;
            *(float2*)(C + (size_t)(r0 + 8) * ldc + cc) = v1;
        }
}

// ---------------- window gather: x(BCHW) -> g_xw[n][s][c] ----------------
__global__ __launch_bounds__(256) void k_gather(const float* __restrict__ x)
{
    __shared__ float tile[64][33];
    int n  = blockIdx.x;
    int ct = blockIdx.y;
    int b  = n / LWIN;
    int wi = n % LWIN;
    int wh = wi / NWD, wwi = wi % NWD;
    int t = threadIdx.x;

    int c_loc = t >> 3;
    int j     = t & 7;
    const float* xb = x + ((size_t)b*CH + ct*32 + c_loc)*HWSZ + (wh*8)*WW + wwi*8 + j;
    #pragma unroll
    for (int i = 0; i < 8; i++)
        tile[i*8 + j][c_loc] = xb[i*WW];
    __syncthreads();

    int c2 = t & 31;
    float* out = g_xw + (size_t)n*(QW*CH) + ct*32 + c2;
    #pragma unroll
    for (int it = 0; it < 8; it++) {
        int s = (t >> 5) + it*8;
        out[s*CH] = tile[s][c2];
    }
}

// ---------------- pool_w[o][c][s] -> g_poolwT[o][s*256+c] ----------------
__global__ __launch_bounds__(256) void k_poolwT(const float* __restrict__ pw)
{
    __shared__ float sm[128*65];
    int o  = blockIdx.x;
    int c0 = blockIdx.y * 128;
    int t  = threadIdx.x;
    const float* p = pw + (size_t)o*16384 + (size_t)c0*64;
    #pragma unroll 4
    for (int i = 0; i < 32; i++) {
        int idx = i*256 + t;
        int c = idx >> 6, s = idx & 63;
        sm[c*65 + s] = p[idx];
    }
    __syncthreads();
    float* out = g_poolwT + (size_t)o*16384 + c0;
    #pragma unroll 4
    for (int i = 0; i < 32; i++) {
        int idx = i*256 + t;
        int s = idx >> 7, c = idx & 127;
        out[s*256 + c] = sm[c*65 + s];
    }
}

// ---------------- split-K reduce for pool (+bias), 32 slices ----------------
__global__ __launch_bounds__(256) void k_pool_reduce(const float* __restrict__ pb)
{
    int idx = blockIdx.x*256 + threadIdx.x;
    float a = pb[idx & 255];
    #pragma unroll
    for (int z = 0; z < 32; z++)
        a += g_poolpart[(size_t)z*(NWIN*CH) + idx];
    g_pool[idx] = a;
}

// ---------------- attention: one block per (window n, head) ----------------
__global__ __launch_bounds__(256) void k_attn(
    const float* __restrict__ gq, const float* __restrict__ gkv, float* __restrict__ gz)
{
    extern __shared__ float sm[];
    float* ks = sm;                   // [144][36]
    float* vs = ks + 144*36;          // [144][36]
    float* qs = vs + 144*36;          // [64][36]
    float* S  = qs + 64*36;           // [64][148]

    int n = blockIdx.x, head = blockIdx.y;
    int bb = n & 7;
    int t = threadIdx.x;

    const float* qsrc = gq + (size_t)n*(QW*CH) + head*HD;
    for (int i = t; i < QW*HD; i += 256) {
        int qi = i >> 5, d = i & 31;
        qs[qi*36 + d] = qsrc[qi*CH + d] * SCALE;
    }
    const float* kvb = gkv + (size_t)bb*(LWIN*2*CH) + head*HD;
    for (int i = t; i < LWIN*HD; i += 256) {
        int l = i >> 5, d = i & 31;
        ks[l*36 + d] = kvb[l*512 + d];
        vs[l*36 + d] = kvb[l*512 + 256 + d];
    }
    __syncthreads();

    int qi = t >> 2, g = t & 3;
    float qv[32];
    #pragma unroll
    for (int d = 0; d < 32; d++) qv[d] = qs[qi*36 + d];

    for (int u = 0; u < 36; u++) {
        int l = g + u*4;
        const float4* kp = (const float4*)(ks + l*36);
        float acc = 0.f;
        #pragma unroll
        for (int d4 = 0; d4 < 8; d4++) {
            float4 kk = kp[d4];
            acc += qv[4*d4+0]*kk.x + qv[4*d4+1]*kk.y
                 + qv[4*d4+2]*kk.z + qv[4*d4+3]*kk.w;
        }
        S[qi*148 + l] = acc;
    }
    __syncthreads();

    if (t < 64) {
        float mx = -1e30f;
        for (int l = 0; l < 144; l++) mx = fmaxf(mx, S[t*148 + l]);
        float sum = 0.f;
        for (int l = 0; l < 144; l++) { float e = __expf(S[t*148+l] - mx); S[t*148+l] = e; sum += e; }
        float inv = 1.f / sum;
        for (int l = 0; l < 144; l++) S[t*148+l] *= inv;
    }
    __syncthreads();

    int d0 = (t & 3) * 8;
    float o[8] = {0,0,0,0,0,0,0,0};
    for (int l = 0; l < 144; l++) {
        float p = S[qi*148 + l];
        const float4* vp = (const float4*)(vs + l*36 + d0);
        float4 v0 = vp[0], v1 = vp[1];
        o[0] += p*v0.x; o[1] += p*v0.y; o[2] += p*v0.z; o[3] += p*v0.w;
        o[4] += p*v1.x; o[5] += p*v1.y; o[6] += p*v1.z; o[7] += p*v1.w;
    }
    float* zo = gz + (size_t)n*(QW*CH) + qi*CH + head*HD + d0;
    float4 s0, s1;
    s0.x=o[0]; s0.y=o[1]; s0.z=o[2]; s0.w=o[3];
    s1.x=o[4]; s1.y=o[5]; s1.z=o[6]; s1.w=o[7];
    *(float4*)zo = s0;
    *(float4*)(zo + 4) = s1;
}

// ---------------- depthwise 3x3 RPE, added into g_z ----------------
__global__ __launch_bounds__(256) void k_rpe(
    const float* __restrict__ x, const float* __restrict__ rw, const float* __restrict__ rb)
{
    unsigned int idx = blockIdx.x*256u + threadIdx.x;
    int w = idx % WW;
    unsigned int r = idx / WW;
    int h = r % HH; r /= HH;
    int c = r & 255;
    int b = r >> 8;

    const float* xp = x + ((size_t)b*CH + c)*HWSZ;
    const float* wp = rw + c*9;
    float acc = rb[c];
    #pragma unroll
    for (int dy = -1; dy <= 1; dy++) {
        int hh = h + dy;
        if (hh < 0 || hh >= HH) continue;
        #pragma unroll
        for (int dx = -1; dx <= 1; dx++) {
            int wc = w + dx;
            if (wc < 0 || wc >= WW) continue;
            acc += xp[hh*WW + wc] * wp[(dy+1)*3 + (dx+1)];
        }
    }
    g_z[idx] += acc;
}

// ---------------- host launch ----------------
extern "C" void kernel_launch(void* const* d_in, const int* in_sizes, int n_in,
                              void* d_out, int out_size)
{
    (void)in_sizes; (void)n_in; (void)out_size;
    const float* x      = (const float*)d_in[0];
    const float* Wq     = (const float*)d_in[1];
    const float* Wkv    = (const float*)d_in[2];
    const float* pool_w = (const float*)d_in[3];
    const float* pool_b = (const float*)d_in[4];
    const float* rpe_w  = (const float*)d_in[5];
    const float* rpe_b  = (const float*)d_in[6];
    const float* proj_w = (const float*)d_in[7];
    const float* proj_b = (const float*)d_in[8];
    float* y = (float*)d_out;

    float *p_xw, *p_q, *p_z, *p_pool, *p_pp, *p_kv, *p_pwt;
    cudaGetSymbolAddress((void**)&p_xw,  g_xw);
    cudaGetSymbolAddress((void**)&p_q,   g_q);
    cudaGetSymbolAddress((void**)&p_z,   g_z);
    cudaGetSymbolAddress((void**)&p_pool,g_pool);
    cudaGetSymbolAddress((void**)&p_pp,  g_poolpart);
    cudaGetSymbolAddress((void**)&p_kv,  g_kv);
    cudaGetSymbolAddress((void**)&p_pwt, g_poolwT);

    const int ATTN_SMEM = (144*36*2 + 64*36 + 64*148) * 4;   // 88,576 B
    cudaFuncSetAttribute(k_attn, cudaFuncAttributeMaxDynamicSharedMemorySize, ATTN_SMEM);

    // 1. window gather
    k_gather<<<dim3(NWIN, 8), 256>>>(x);
    // 2. transpose pool weights
    k_poolwT<<<dim3(CH, 2), 256>>>(pool_w);
    // 3. pool GEMM: [1152,16384] x poolwT^T, split-K=32 -> partials, then reduce+bias
    k_gemm_mma<<<dim3(2, 9, 32), 256>>>(p_xw, p_pwt, p_pp, nullptr,
                                        NWIN, QW*CH, CH, 512);
    k_pool_reduce<<<NWIN, 256>>>(pool_b);
    // 4. Q projection: [73728,256] x Wq^T
    k_gemm_mma<<<dim3(2, 576, 1), 256>>>(p_xw, Wq, p_q, nullptr,
                                         NWIN*QW, CH, CH, CH);
    // 5. KV projection: [1152,256] x Wkv^T -> [1152,512]
    k_gemm_mma<<<dim3(4, 9, 1), 256>>>(p_pool, Wkv, p_kv, nullptr,
                                       NWIN, CH, 2*CH, CH);
    // 6. attention per (window, head) -> g_z
    k_attn<<<dim3(NWIN, NHEAD), 256, ATTN_SMEM>>>(p_q, p_kv, p_z);
    // 7. RPE depthwise conv accumulate into g_z
    k_rpe<<<(NWIN*QW*CH)/256, 256>>>(x, rpe_w, rpe_b);
    // 8. output projection + bias -> d_out
    k_gemm_mma<<<dim3(2, 576, 1), 256>>>(p_z, proj_w, y, proj_b,
                                         NWIN*QW, CH, CH, CH);
}

// round 16
// speedup vs baseline: 1.8571x; 1.8571x over previous
#include <cuda_runtime.h>
#include <cuda_bf16.h>
#include <cstdint>

// ---------------- problem constants ----------------
#define BATCH 8
#define CH    256
#define HH    96
#define WW    96
#define HWSZ  (HH*WW)        // 9216
#define NWD   12
#define LWIN  144
#define NWIN  1152
#define QW    64
#define NHEAD 8
#define HD    32
#define SCALE 0.1767766952966369f

// ---------------- device scratch ----------------
__device__ __nv_bfloat16 g_xw_h[NWIN*QW*CH];   // window-gathered x, bf16 hi
__device__ __nv_bfloat16 g_xw_l[NWIN*QW*CH];   // bf16 lo residual
__device__ float g_q [NWIN*QW*CH];             // Q projection (fp32)
__device__ float g_z [NWIN*QW*CH];             // attn out + rpe (BCHW-flat)
__device__ float g_poolpart[32*NWIN*CH];       // split-K partials
__device__ __nv_bfloat16 g_pool_h[NWIN*CH];
__device__ __nv_bfloat16 g_pool_l[NWIN*CH];
__device__ float g_kv[NWIN*2*CH];              // [bl][t*256 + head*32 + d]
__device__ __nv_bfloat16 g_pwt_h[CH*QW*CH];    // pool_w -> [o][s*256+c]
__device__ __nv_bfloat16 g_pwt_l[CH*QW*CH];
__device__ __nv_bfloat16 g_wq_h[CH*CH];
__device__ __nv_bfloat16 g_wq_l[CH*CH];
__device__ __nv_bfloat16 g_wkv_h[2*CH*CH];
__device__ __nv_bfloat16 g_wkv_l[2*CH*CH];

// ---------------- helpers ----------------
__device__ __forceinline__ uint32_t smem_u32(const void* p) {
    uint32_t a;
    asm("{ .reg .u64 t; cvta.to.shared.u64 t, %1; cvt.u32.u64 %0, t; }" : "=r"(a) : "l"(p));
    return a;
}
__device__ __forceinline__ void ldsm4(uint32_t* r, uint32_t addr) {
    asm volatile("ldmatrix.sync.aligned.m8n8.x4.shared.b16 {%0,%1,%2,%3}, [%4];"
        : "=r"(r[0]), "=r"(r[1]), "=r"(r[2]), "=r"(r[3]) : "r"(addr));
}
__device__ __forceinline__ void mma16816(float* c, const uint32_t* a, const uint32_t* b) {
    asm volatile("mma.sync.aligned.m16n8k16.row.col.f32.bf16.bf16.f32 "
        "{%0,%1,%2,%3}, {%4,%5,%6,%7}, {%8,%9}, {%0,%1,%2,%3};"
        : "+f"(c[0]), "+f"(c[1]), "+f"(c[2]), "+f"(c[3])
        : "r"(a[0]), "r"(a[1]), "r"(a[2]), "r"(a[3]), "r"(b[0]), "r"(b[1]));
}
__device__ __forceinline__ void split_hl(float v, __nv_bfloat16& h, __nv_bfloat16& l) {
    h = __float2bfloat16(v);
    l = __float2bfloat16(v - __bfloat162float(h));
}
__device__ __forceinline__ void pack2_hl(float x, float y, uint32_t& h, uint32_t& l) {
    __nv_bfloat16 hx, lx, hy, ly;
    split_hl(x, hx, lx); split_hl(y, hy, ly);
    h = ((uint32_t)__bfloat16_as_ushort(hy) << 16) | __bfloat16_as_ushort(hx);
    l = ((uint32_t)__bfloat16_as_ushort(ly) << 16) | __bfloat16_as_ushort(lx);
}
__device__ __forceinline__ void cvt_hl4(float4 v, uint2& h, uint2& l) {
    pack2_hl(v.x, v.y, h.x, l.x);
    pack2_hl(v.z, v.w, h.y, l.y);
}

// =============== HMMA NT GEMM, bf16 hi/lo preconverted inputs ===============
// C[m,n] = sum_k A[m*K+k]*B[n*K+k], 3-pass hi/lo. 128x128 tile, BK=32, 8 warps.
__global__ __launch_bounds__(256) void k_gemm_bf(
    const __nv_bfloat16* __restrict__ AH, const __nv_bfloat16* __restrict__ AL,
    const __nv_bfloat16* __restrict__ BH, const __nv_bfloat16* __restrict__ BL,
    float* __restrict__ C, const float* __restrict__ bias,
    int M, int K, int ldc, int kcount)
{
    __shared__ __align__(16) __nv_bfloat16 AsH[128][40];
    __shared__ __align__(16) __nv_bfloat16 AsL[128][40];
    __shared__ __align__(16) __nv_bfloat16 BsH[128][40];
    __shared__ __align__(16) __nv_bfloat16 BsL[128][40];

    const int t    = threadIdx.x;
    const int lane = t & 31;
    const int wid  = t >> 5;
    const int n0 = blockIdx.x * 128;
    const int m0 = blockIdx.y * 128;
    const int k0 = blockIdx.z * kcount;
    C += (size_t)blockIdx.z * M * ldc + (size_t)m0 * ldc + n0;
    const float* bp = bias ? bias + n0 : nullptr;

    const int wm = (wid >> 2) * 64;
    const int wn = (wid & 3) * 32;

    const uint32_t aH_base = smem_u32(AsH), aL_base = smem_u32(AsL);
    const uint32_t bH_base = smem_u32(BsH), bL_base = smem_u32(BsL);

    float acc[4][4][4] = {};

    const int r  = t >> 1;           // 0..127 tile row
    const int hf = (t & 1) << 4;     // col half: 0 or 16 (this thread owns 16 cols)
    const __nv_bfloat16* Ahp = AH + (size_t)(m0 + r) * K + k0 + hf;
    const __nv_bfloat16* Alp = AL + (size_t)(m0 + r) * K + k0 + hf;
    const __nv_bfloat16* Bhp = BH + (size_t)(n0 + r) * K + k0 + hf;
    const __nv_bfloat16* Blp = BL + (size_t)(n0 + r) * K + k0 + hf;

    const int nChunks = kcount >> 5;
    for (int c = 0; c < nChunks; c++) {
        const int off = c * 32;
        // each thread: 16 cols per array (2x uint4) -> full 128x32 tile coverage
        uint4 a0 = *(const uint4*)(Ahp + off);
        uint4 a1 = *(const uint4*)(Ahp + off + 8);
        uint4 b0 = *(const uint4*)(Alp + off);
        uint4 b1 = *(const uint4*)(Alp + off + 8);
        uint4 c0 = *(const uint4*)(Bhp + off);
        uint4 c1 = *(const uint4*)(Bhp + off + 8);
        uint4 d0 = *(const uint4*)(Blp + off);
        uint4 d1 = *(const uint4*)(Blp + off + 8);
        char* pA = (char*)AsH + r * 80 + hf * 2;
        char* pB = (char*)AsL + r * 80 + hf * 2;
        char* pC = (char*)BsH + r * 80 + hf * 2;
        char* pD = (char*)BsL + r * 80 + hf * 2;
        *(uint4*)pA = a0; *(uint4*)(pA + 16) = a1;
        *(uint4*)pB = b0; *(uint4*)(pB + 16) = b1;
        *(uint4*)pC = c0; *(uint4*)(pC + 16) = c1;
        *(uint4*)pD = d0; *(uint4*)(pD + 16) = d1;
        __syncthreads();

        #pragma unroll
        for (int kk = 0; kk < 32; kk += 16) {
            uint32_t aH[4][4], aL[4][4], bH[2][4], bL[2][4];
            #pragma unroll
            for (int mi = 0; mi < 4; mi++) {
                uint32_t aoff = (uint32_t)((wm + mi * 16 + (lane & 15)) * 80
                                          + (kk + ((lane >> 4) << 3)) * 2);
                ldsm4(aH[mi], aH_base + aoff);
                ldsm4(aL[mi], aL_base + aoff);
            }
            #pragma unroll
            for (int nj = 0; nj < 2; nj++) {
                uint32_t boff = (uint32_t)((wn + nj * 16 + ((lane >> 4) << 3) + (lane & 7)) * 80
                                          + (kk + (((lane >> 3) & 1) << 3)) * 2);
                ldsm4(bH[nj], bH_base + boff);
                ldsm4(bL[nj], bL_base + boff);
            }
            #pragma unroll
            for (int mi = 0; mi < 4; mi++)
                #pragma unroll
                for (int ni = 0; ni < 4; ni++) {
                    const uint32_t* bh = &bH[ni >> 1][(ni & 1) * 2];
                    const uint32_t* bl = &bL[ni >> 1][(ni & 1) * 2];
                    mma16816(acc[mi][ni], aH[mi], bh);
                    mma16816(acc[mi][ni], aH[mi], bl);
                    mma16816(acc[mi][ni], aL[mi], bh);
                }
        }
        __syncthreads();
    }

    #pragma unroll
    for (int mi = 0; mi < 4; mi++)
        #pragma unroll
        for (int ni = 0; ni < 4; ni++) {
            int r0 = wm + mi * 16 + (lane >> 2);
            int cc = wn + ni * 8 + (lane & 3) * 2;
            float b0 = 0.f, b1 = 0.f;
            if (bp) { b0 = bp[cc]; b1 = bp[cc + 1]; }
            *(float2*)(C + (size_t)r0 * ldc + cc) =
                make_float2(acc[mi][ni][0] + b0, acc[mi][ni][1] + b1);
            *(float2*)(C + (size_t)(r0 + 8) * ldc + cc) =
                make_float2(acc[mi][ni][2] + b0, acc[mi][ni][3] + b1);
        }
}

// =============== HMMA NT GEMM with fp32 inputs (cvt on load) — for proj ===============
__global__ __launch_bounds__(256) void k_gemm_mma(
    const float* __restrict__ A, const float* __restrict__ B,
    float* __restrict__ C, const float* __restrict__ bias,
    int M, int K, int ldc, int kcount)
{
    __shared__ __align__(16) __nv_bfloat16 AsH[128][40];
    __shared__ __align__(16) __nv_bfloat16 AsL[128][40];
    __shared__ __align__(16) __nv_bfloat16 BsH[128][40];
    __shared__ __align__(16) __nv_bfloat16 BsL[128][40];

    const int t    = threadIdx.x;
    const int lane = t & 31;
    const int wid  = t >> 5;
    const int n0 = blockIdx.x * 128;
    const int m0 = blockIdx.y * 128;
    A += (size_t)m0 * K;
    B += (size_t)n0 * K;
    C += (size_t)m0 * ldc + n0;
    const float* bp = bias ? bias + n0 : nullptr;

    const int wm = (wid >> 2) * 64;
    const int wn = (wid & 3) * 32;

    const uint32_t aH_base = smem_u32(AsH), aL_base = smem_u32(AsL);
    const uint32_t bH_base = smem_u32(BsH), bL_base = smem_u32(BsL);

    float acc[4][4][4] = {};
    const int rb = t >> 3;
    const int jb = t & 7;

    const int nChunks = kcount >> 5;
    for (int c = 0; c < nChunks; c++) {
        const float* Ag = A + c * 32;
        const float* Bg = B + c * 32;
        #pragma unroll
        for (int it = 0; it < 4; it++) {
            int r = it * 32 + rb;
            float4 va = *(const float4*)(Ag + (size_t)r * K + jb * 4);
            float4 vb = *(const float4*)(Bg + (size_t)r * K + jb * 4);
            uint2 h, l;
            cvt_hl4(va, h, l);
            *(uint2*)((char*)AsH + r * 80 + jb * 8) = h;
            *(uint2*)((char*)AsL + r * 80 + jb * 8) = l;
            cvt_hl4(vb, h, l);
            *(uint2*)((char*)BsH + r * 80 + jb * 8) = h;
            *(uint2*)((char*)BsL + r * 80 + jb * 8) = l;
        }
        __syncthreads();

        #pragma unroll
        for (int kk = 0; kk < 32; kk += 16) {
            uint32_t aH[4][4], aL[4][4], bH[2][4], bL[2][4];
            #pragma unroll
            for (int mi = 0; mi < 4; mi++) {
                uint32_t off = (uint32_t)((wm + mi * 16 + (lane & 15)) * 80
                                          + (kk + ((lane >> 4) << 3)) * 2);
                ldsm4(aH[mi], aH_base + off);
                ldsm4(aL[mi], aL_base + off);
            }
            #pragma unroll
            for (int nj = 0; nj < 2; nj++) {
                uint32_t off = (uint32_t)((wn + nj * 16 + ((lane >> 4) << 3) + (lane & 7)) * 80
                                          + (kk + (((lane >> 3) & 1) << 3)) * 2);
                ldsm4(bH[nj], bH_base + off);
                ldsm4(bL[nj], bL_base + off);
            }
            #pragma unroll
            for (int mi = 0; mi < 4; mi++)
                #pragma unroll
                for (int ni = 0; ni < 4; ni++) {
                    const uint32_t* bh = &bH[ni >> 1][(ni & 1) * 2];
                    const uint32_t* bl = &bL[ni >> 1][(ni & 1) * 2];
                    mma16816(acc[mi][ni], aH[mi], bh);
                    mma16816(acc[mi][ni], aH[mi], bl);
                    mma16816(acc[mi][ni], aL[mi], bh);
                }
        }
        __syncthreads();
    }

    #pragma unroll
    for (int mi = 0; mi < 4; mi++)
        #pragma unroll
        for (int ni = 0; ni < 4; ni++) {
            int r0 = wm + mi * 16 + (lane >> 2);
            int cc = wn + ni * 8 + (lane & 3) * 2;
            float b0 = 0.f, b1 = 0.f;
            if (bp) { b0 = bp[cc]; b1 = bp[cc + 1]; }
            *(float2*)(C + (size_t)r0 * ldc + cc) =
                make_float2(acc[mi][ni][0] + b0, acc[mi][ni][1] + b1);
            *(float2*)(C + (size_t)(r0 + 8) * ldc + cc) =
                make_float2(acc[mi][ni][2] + b0, acc[mi][ni][3] + b1);
        }
}

// =============== HMMA attention: block per (window, head), 4 warps x 16 rows ===============
__global__ __launch_bounds__(128) void k_attn_mma(
    const float* __restrict__ gq, const float* __restrict__ gkv, float* __restrict__ gz)
{
    extern __shared__ __align__(16) __nv_bfloat16 smb[];
    __nv_bfloat16* qh  = smb;              // [64][40]
    __nv_bfloat16* ql  = qh  + 64*40;
    __nv_bfloat16* kh  = ql  + 64*40;      // [144][40]
    __nv_bfloat16* kl  = kh  + 144*40;
    __nv_bfloat16* vth = kl  + 144*40;     // V^T [32][152]
    __nv_bfloat16* vtl = vth + 32*152;

    const int n = blockIdx.x, head = blockIdx.y;
    const int bb = n & 7;
    const int t = threadIdx.x;
    const int lane = t & 31, wid = t >> 5;

    // Q (scaled) -> hi/lo
    const float* qsrc = gq + (size_t)n*(QW*CH) + head*HD;
    #pragma unroll
    for (int i = t; i < QW*HD; i += 128) {
        int qi = i >> 5, d = i & 31;
        float v = qsrc[qi*CH + d] * SCALE;
        split_hl(v, qh[qi*40 + d], ql[qi*40 + d]);
    }
    // K rows + V transposed
    const float* kvb = gkv + (size_t)bb*(LWIN*2*CH) + head*HD;
    #pragma unroll
    for (int i = t; i < LWIN*HD; i += 128) {
        int l = i >> 5, d = i & 31;
        float kvl = kvb[l*512 + d];
        split_hl(kvl, kh[l*40 + d], kl[l*40 + d]);
        float vv = kvb[l*512 + 256 + d];
        split_hl(vv, vth[d*152 + l], vtl[d*152 + l]);
    }
    __syncthreads();

    const uint32_t qh_b = smem_u32(qh), ql_b = smem_u32(ql);
    const uint32_t kh_b = smem_u32(kh), kl_b = smem_u32(kl);
    const uint32_t vh_b = smem_u32(vth), vl_b = smem_u32(vtl);
    const int wm = wid * 16;

    // -------- S = Q K^T : acc[18][4], 18 n8 tiles over 144 keys --------
    float acc[18][4];
    #pragma unroll
    for (int i = 0; i < 18; i++) { acc[i][0]=acc[i][1]=acc[i][2]=acc[i][3]=0.f; }

    #pragma unroll
    for (int kk = 0; kk < 32; kk += 16) {
        uint32_t aH[4], aL[4];
        uint32_t aoff = (uint32_t)((wm + (lane & 15)) * 80 + (kk + ((lane >> 4) << 3)) * 2);
        ldsm4(aH, qh_b + aoff);
        ldsm4(aL, ql_b + aoff);
        #pragma unroll
        for (int nj = 0; nj < 9; nj++) {
            uint32_t bH[4], bL[4];
            uint32_t boff = (uint32_t)((nj*16 + ((lane >> 4) << 3) + (lane & 7)) * 80
                                      + (kk + (((lane >> 3) & 1) << 3)) * 2);
            ldsm4(bH, kh_b + boff);
            ldsm4(bL, kl_b + boff);
            #pragma unroll
            for (int s = 0; s < 2; s++) {
                int ni = nj*2 + s;
                mma16816(acc[ni], aH, &bH[s*2]);
                mma16816(acc[ni], aH, &bL[s*2]);
                mma16816(acc[ni], aL, &bH[s*2]);
            }
        }
    }

    // -------- softmax in registers (rows r=lane>>2 and r+8) --------
    float mx0 = -1e30f, mx1 = -1e30f;
    #pragma unroll
    for (int ni = 0; ni < 18; ni++) {
        mx0 = fmaxf(mx0, fmaxf(acc[ni][0], acc[ni][1]));
        mx1 = fmaxf(mx1, fmaxf(acc[ni][2], acc[ni][3]));
    }
    mx0 = fmaxf(mx0, __shfl_xor_sync(0xffffffffu, mx0, 1));
    mx0 = fmaxf(mx0, __shfl_xor_sync(0xffffffffu, mx0, 2));
    mx1 = fmaxf(mx1, __shfl_xor_sync(0xffffffffu, mx1, 1));
    mx1 = fmaxf(mx1, __shfl_xor_sync(0xffffffffu, mx1, 2));
    float s0 = 0.f, s1 = 0.f;
    #pragma unroll
    for (int ni = 0; ni < 18; ni++) {
        acc[ni][0] = __expf(acc[ni][0] - mx0); s0 += acc[ni][0];
        acc[ni][1] = __expf(acc[ni][1] - mx0); s0 += acc[ni][1];
        acc[ni][2] = __expf(acc[ni][2] - mx1); s1 += acc[ni][2];
        acc[ni][3] = __expf(acc[ni][3] - mx1); s1 += acc[ni][3];
    }
    s0 += __shfl_xor_sync(0xffffffffu, s0, 1);
    s0 += __shfl_xor_sync(0xffffffffu, s0, 2);
    s1 += __shfl_xor_sync(0xffffffffu, s1, 1);
    s1 += __shfl_xor_sync(0xffffffffu, s1, 2);
    float inv0 = 1.f / s0, inv1 = 1.f / s1;
    #pragma unroll
    for (int ni = 0; ni < 18; ni++) {
        acc[ni][0] *= inv0; acc[ni][1] *= inv0;
        acc[ni][2] *= inv1; acc[ni][3] *= inv1;
    }

    // -------- pack P into A-fragments (hi/lo), registers only --------
    uint32_t pH[9][4], pL[9][4];
    #pragma unroll
    for (int j = 0; j < 9; j++) {
        pack2_hl(acc[2*j][0],   acc[2*j][1],   pH[j][0], pL[j][0]);
        pack2_hl(acc[2*j][2],   acc[2*j][3],   pH[j][1], pL[j][1]);
        pack2_hl(acc[2*j+1][0], acc[2*j+1][1], pH[j][2], pL[j][2]);
        pack2_hl(acc[2*j+1][2], acc[2*j+1][3], pH[j][3], pL[j][3]);
    }

    // -------- O = P V : 4 n8 tiles over 32 head-dims --------
    float o[4][4] = {};
    #pragma unroll
    for (int j = 0; j < 9; j++) {
        #pragma unroll
        for (int nj = 0; nj < 2; nj++) {
            uint32_t bH[4], bL[4];
            uint32_t boff = (uint32_t)((nj*16 + ((lane >> 4) << 3) + (lane & 7)) * 304
                                      + (j*16 + (((lane >> 3) & 1) << 3)) * 2);
            ldsm4(bH, vh_b + boff);
            ldsm4(bL, vl_b + boff);
            #pragma unroll
            for (int s = 0; s < 2; s++) {
                int ni = nj*2 + s;
                mma16816(o[ni], pH[j], &bH[s*2]);
                mma16816(o[ni], pH[j], &bL[s*2]);
                mma16816(o[ni], pL[j], &bH[s*2]);
            }
        }
    }

    // -------- write O to g_z (flat: n*16384 + q*256 + head*32 + d) --------
    const int r = wm + (lane >> 2), cb = (lane & 3) * 2;
    float* zbase = gz + (size_t)n*(QW*CH) + head*HD;
    #pragma unroll
    for (int ni = 0; ni < 4; ni++) {
        *(float2*)(zbase + (size_t)r*CH + ni*8 + cb)       = make_float2(o[ni][0], o[ni][1]);
        *(float2*)(zbase + (size_t)(r+8)*CH + ni*8 + cb)   = make_float2(o[ni][2], o[ni][3]);
    }
}

// ---------------- window gather: x(BCHW) -> xw hi/lo [n][s][c] ----------------
__global__ __launch_bounds__(256) void k_gather(const float* __restrict__ x)
{
    __shared__ float tile[64][33];
    int n  = blockIdx.x;
    int ct = blockIdx.y;
    int b  = n / LWIN;
    int wi = n % LWIN;
    int wh = wi / NWD, wwi = wi % NWD;
    int t = threadIdx.x;

    int c_loc = t >> 3;
    int j     = t & 7;
    const float* xb = x + ((size_t)b*CH + ct*32 + c_loc)*HWSZ + (wh*8)*WW + wwi*8 + j;
    #pragma unroll
    for (int i = 0; i < 8; i++)
        tile[i*8 + j][c_loc] = xb[i*WW];
    __syncthreads();

    int c2 = t & 31;
    size_t base = (size_t)n*(QW*CH) + ct*32 + c2;
    #pragma unroll
    for (int it = 0; it < 8; it++) {
        int s = (t >> 5) + it*8;
        float v = tile[s][c2];
        split_hl(v, g_xw_h[base + s*CH], g_xw_l[base + s*CH]);
    }
}

// ---------------- pool_w[o][c][s] -> poolwT hi/lo [o][s*256+c] ----------------
__global__ __launch_bounds__(256) void k_poolwT(const float* __restrict__ pw)
{
    __shared__ float sm[128*65];
    int o  = blockIdx.x;
    int c0 = blockIdx.y * 128;
    int t  = threadIdx.x;
    const float* p = pw + (size_t)o*16384 + (size_t)c0*64;
    #pragma unroll 4
    for (int i = 0; i < 32; i++) {
        int idx = i*256 + t;
        int c = idx >> 6, s = idx & 63;
        sm[c*65 + s] = p[idx];
    }
    __syncthreads();
    size_t ob = (size_t)o*16384 + c0;
    #pragma unroll 4
    for (int i = 0; i < 32; i++) {
        int idx = i*256 + t;
        int s = idx >> 7, c = idx & 127;
        split_hl(sm[c*65 + s], g_pwt_h[ob + s*256 + c], g_pwt_l[ob + s*256 + c]);
    }
}

// ---------------- generic fp32 -> bf16 hi/lo conversion ----------------
__global__ __launch_bounds__(256) void k_cvt(
    const float* __restrict__ src, __nv_bfloat16* __restrict__ h,
    __nv_bfloat16* __restrict__ l, int nelem)
{
    int idx = blockIdx.x*256 + threadIdx.x;
    if (idx < nelem) split_hl(src[idx], h[idx], l[idx]);
}

// ---------------- split-K reduce for pool (+bias) -> hi/lo ----------------
__global__ __launch_bounds__(256) void k_pool_reduce(const float* __restrict__ pb)
{
    int idx = blockIdx.x*256 + threadIdx.x;
    float a = pb[idx & 255];
    #pragma unroll
    for (int z = 0; z < 32; z++)
        a += g_poolpart[(size_t)z*(NWIN*CH) + idx];
    split_hl(a, g_pool_h[idx], g_pool_l[idx]);
}

// ---------------- depthwise 3x3 RPE, added into g_z ----------------
__global__ __launch_bounds__(256) void k_rpe(
    const float* __restrict__ x, const float* __restrict__ rw, const float* __restrict__ rb)
{
    unsigned int idx = blockIdx.x*256u + threadIdx.x;
    int w = idx % WW;
    unsigned int r = idx / WW;
    int h = r % HH; r /= HH;
    int c = r & 255;
    int b = r >> 8;

    const float* xp = x + ((size_t)b*CH + c)*HWSZ;
    const float* wp = rw + c*9;
    float acc = rb[c];
    #pragma unroll
    for (int dy = -1; dy <= 1; dy++) {
        int hh = h + dy;
        if (hh < 0 || hh >= HH) continue;
        #pragma unroll
        for (int dx = -1; dx <= 1; dx++) {
            int wc = w + dx;
            if (wc < 0 || wc >= WW) continue;
            acc += xp[hh*WW + wc] * wp[(dy+1)*3 + (dx+1)];
        }
    }
    g_z[idx] += acc;
}

// ---------------- host launch ----------------
extern "C" void kernel_launch(void* const* d_in, const int* in_sizes, int n_in,
                              void* d_out, int out_size)
{
    (void)in_sizes; (void)n_in; (void)out_size;
    const float* x      = (const float*)d_in[0];
    const float* Wq     = (const float*)d_in[1];
    const float* Wkv    = (const float*)d_in[2];
    const float* pool_w = (const float*)d_in[3];
    const float* pool_b = (const float*)d_in[4];
    const float* rpe_w  = (const float*)d_in[5];
    const float* rpe_b  = (const float*)d_in[6];
    const float* proj_w = (const float*)d_in[7];
    const float* proj_b = (const float*)d_in[8];
    float* y = (float*)d_out;

    __nv_bfloat16 *p_xwh, *p_xwl, *p_pwth, *p_pwtl, *p_wqh, *p_wql, *p_wkvh, *p_wkvl,
                  *p_ph, *p_pl;
    float *p_q, *p_z, *p_pp, *p_kv;
    cudaGetSymbolAddress((void**)&p_xwh, g_xw_h);
    cudaGetSymbolAddress((void**)&p_xwl, g_xw_l);
    cudaGetSymbolAddress((void**)&p_q,   g_q);
    cudaGetSymbolAddress((void**)&p_z,   g_z);
    cudaGetSymbolAddress((void**)&p_pp,  g_poolpart);
    cudaGetSymbolAddress((void**)&p_kv,  g_kv);
    cudaGetSymbolAddress((void**)&p_pwth, g_pwt_h);
    cudaGetSymbolAddress((void**)&p_pwtl, g_pwt_l);
    cudaGetSymbolAddress((void**)&p_wqh, g_wq_h);
    cudaGetSymbolAddress((void**)&p_wql, g_wq_l);
    cudaGetSymbolAddress((void**)&p_wkvh, g_wkv_h);
    cudaGetSymbolAddress((void**)&p_wkvl, g_wkv_l);
    cudaGetSymbolAddress((void**)&p_ph, g_pool_h);
    cudaGetSymbolAddress((void**)&p_pl, g_pool_l);

    const int ATTN_SMEM = (64*40*2 + 144*40*2 + 32*152*2) * 2;   // 52,736 B
    cudaFuncSetAttribute(k_attn_mma, cudaFuncAttributeMaxDynamicSharedMemorySize, ATTN_SMEM);

    // 1. window gather -> bf16 hi/lo
    k_gather<<<dim3(NWIN, 8), 256>>>(x);
    // 2. transpose pool weights -> hi/lo
    k_poolwT<<<dim3(CH, 2), 256>>>(pool_w);
    // 2b. convert Wq, Wkv
    k_cvt<<<(CH*CH)/256, 256>>>(Wq, p_wqh, p_wql, CH*CH);
    k_cvt<<<(2*CH*CH)/256, 256>>>(Wkv, p_wkvh, p_wkvl, 2*CH*CH);
    // 3. pool GEMM split-K=32, then reduce+bias -> hi/lo
    k_gemm_bf<<<dim3(2, 9, 32), 256>>>(p_xwh, p_xwl, p_pwth, p_pwtl, p_pp, nullptr,
                                       NWIN, QW*CH, CH, 512);
    k_pool_reduce<<<NWIN, 256>>>(pool_b);
    // 4. Q projection
    k_gemm_bf<<<dim3(2, 576, 1), 256>>>(p_xwh, p_xwl, p_wqh, p_wql, p_q, nullptr,
                                        NWIN*QW, CH, CH, CH);
    // 5. KV projection
    k_gemm_bf<<<dim3(4, 9, 1), 256>>>(p_ph, p_pl, p_wkvh, p_wkvl, p_kv, nullptr,
                                      NWIN, CH, 2*CH, CH);
    // 6. HMMA attention -> g_z
    k_attn_mma<<<dim3(NWIN, NHEAD), 128, ATTN_SMEM>>>(p_q, p_kv, p_z);
    // 7. RPE accumulate into g_z
    k_rpe<<<(NWIN*QW*CH)/256, 256>>>(x, rpe_w, rpe_b);
    // 8. output projection + bias -> d_out (fp32 input path)
    k_gemm_mma<<<dim3(2, 576, 1), 256>>>(p_z, proj_w, y, proj_b,
                                         NWIN*QW, CH, CH, CH);
}